// round 8
// baseline (speedup 1.0000x reference)
#include <cuda_runtime.h>
#include <cuda_fp16.h>
#include <math.h>
#include <stdint.h>

#define D 128
#define R 16
#define KTOT 2176          // 16*128 relation cols + 128 self cols
#define MPAD 50048         // 391 * 128
#define NMAX 50000
#define EMAX 800000

// ---------------- scratch (device globals; allocation-free) ----------------
__device__ __half g_aggx[(size_t)MPAD * KTOT];      // 218 MB: [Agg_0..Agg_15, x] fp16
__device__ float g_x[(size_t)MPAD * 128];
__device__ __half g_Bh2[128 * KTOT];                // [dout][kglob] hi
__device__ __half g_Bl2[128 * KTOT];                // lo residual
__device__ float g_seq[256 * 4 * 256];
__device__ float g_WT[2][384 * 512];
__device__ float g_h[2 * 256 * 128];
// CSR
__device__ int g_cnt[NMAX];
__device__ int g_off[NMAX + 1];
__device__ int g_cur[NMAX];
__device__ uint32_t g_sed[EMAX];   // packed src | (r<<16)

// ---------------- bit-cast helpers ----------------
__device__ __forceinline__ uint32_t h2_as_u32(__half2 h) {
    uint32_t u; *(__half2*)&u = h; return u;
}

// ---------------- PTX helpers ----------------
__device__ __forceinline__ uint32_t smem_u32(const void* p) {
    return (uint32_t)__cvta_generic_to_shared(p);
}
__device__ __forceinline__ void ldm_x4(uint32_t& r0, uint32_t& r1, uint32_t& r2, uint32_t& r3,
                                       uint32_t a) {
    asm volatile("ldmatrix.sync.aligned.m8n8.x4.shared.b16 {%0,%1,%2,%3}, [%4];"
                 : "=r"(r0), "=r"(r1), "=r"(r2), "=r"(r3) : "r"(a));
}
__device__ __forceinline__ void ldm_x2(uint32_t& r0, uint32_t& r1, uint32_t a) {
    asm volatile("ldmatrix.sync.aligned.m8n8.x2.shared.b16 {%0,%1}, [%2];"
                 : "=r"(r0), "=r"(r1) : "r"(a));
}
__device__ __forceinline__ void mma16816(float* c, uint32_t a0, uint32_t a1, uint32_t a2,
                                         uint32_t a3, uint32_t b0, uint32_t b1) {
    asm volatile(
        "mma.sync.aligned.m16n8k16.row.col.f32.f16.f16.f32 "
        "{%0,%1,%2,%3}, {%4,%5,%6,%7}, {%8,%9}, {%0,%1,%2,%3};"
        : "+f"(c[0]), "+f"(c[1]), "+f"(c[2]), "+f"(c[3])
        : "r"(a0), "r"(a1), "r"(a2), "r"(a3), "r"(b0), "r"(b1));
}

// ---------------- CSR build ----------------
__global__ void k_zero_cnt(int N) {
    int i = blockIdx.x * blockDim.x + threadIdx.x;
    if (i < N) g_cnt[i] = 0;
}
__global__ void k_hist(const int* __restrict__ dst, int E) {
    int e = blockIdx.x * blockDim.x + threadIdx.x;
    if (e < E) atomicAdd(&g_cnt[dst[e]], 1);
}
__global__ __launch_bounds__(1024) void k_scan(int N) {
    __shared__ int sh[1024];
    int t = threadIdx.x;
    int chunk = (N + 1023) / 1024;
    int c0 = t * chunk, c1 = min(c0 + chunk, N);
    int s = 0;
    for (int i = c0; i < c1; i++) s += g_cnt[i];
    sh[t] = s;
    __syncthreads();
    for (int o = 1; o < 1024; o <<= 1) {
        int v = (t >= o) ? sh[t - o] : 0;
        __syncthreads();
        sh[t] += v;
        __syncthreads();
    }
    int run = sh[t] - s;
    for (int i = c0; i < c1; i++) {
        g_off[i] = run;
        g_cur[i] = run;
        run += g_cnt[i];
    }
    if (t == 1023) g_off[N] = run;
}
__global__ void k_place(const int* __restrict__ src, const int* __restrict__ dst,
                        const int* __restrict__ et, int E) {
    int e = blockIdx.x * blockDim.x + threadIdx.x;
    if (e >= E) return;
    int pos = atomicAdd(&g_cur[dst[e]], 1);
    g_sed[pos] = (uint32_t)src[e] | ((uint32_t)et[e] << 16);
}

// ---------------- pack weights: B2[dout][kglob] hi/lo ----------------
__global__ void k_packb2(const float* __restrict__ Wrel, const float* __restrict__ Wself) {
    int idx = blockIdx.x * blockDim.x + threadIdx.x;
    if (idx >= 128 * KTOT) return;
    int dout = idx / KTOT, kg = idx % KTOT;
    float v;
    if (kg < 2048) {
        int r = kg >> 7, d = kg & 127;
        v = Wrel[((size_t)r * 128 + d) * 128 + dout];
    } else {
        v = Wself[(kg - 2048) * 128 + dout];
    }
    __half h = __float2half_rn(v);
    g_Bh2[idx] = h;
    g_Bl2[idx] = __float2half_rn(v - __half2float(h));
}

// ---------------- aggregation: warp per node, relation buckets in registers ----------------
#define CASE_R(rr) case rr: acc[rr][0] += xv.x; acc[rr][1] += xv.y; \
                            acc[rr][2] += xv.z; acc[rr][3] += xv.w; break;

__global__ __launch_bounds__(256) void k_aggr(const float* __restrict__ x0, int layer, int Nn) {
    int n = blockIdx.x * 8 + (threadIdx.x >> 5);
    int lane = threadIdx.x & 31;
    if (n >= MPAD) return;
    __half* out = g_aggx + (size_t)n * KTOT;
    if (n >= Nn) {
        // zero row (17 * 8B per lane)
        uint2 z = make_uint2(0u, 0u);
#pragma unroll
        for (int i = 0; i < 17; i++)
            *(uint2*)(out + i * 128 + lane * 4) = z;
        return;
    }
    const float* x = (layer == 0) ? x0 : (const float*)g_x;
    int beg = g_off[n], end = g_off[n + 1];

    float acc[16][4];
#pragma unroll
    for (int r = 0; r < 16; r++)
#pragma unroll
        for (int q = 0; q < 4; q++) acc[r][q] = 0.0f;

    int e = beg;
    for (; e + 2 <= end; e += 2) {
        uint32_t p0 = g_sed[e], p1 = g_sed[e + 1];
        float4 xv0 = *(const float4*)(x + (size_t)(p0 & 0xFFFF) * 128 + lane * 4);
        float4 xv1 = *(const float4*)(x + (size_t)(p1 & 0xFFFF) * 128 + lane * 4);
        {
            float4 xv = xv0;
            switch (p0 >> 16) {
                CASE_R(0) CASE_R(1) CASE_R(2) CASE_R(3) CASE_R(4) CASE_R(5) CASE_R(6) CASE_R(7)
                CASE_R(8) CASE_R(9) CASE_R(10) CASE_R(11) CASE_R(12) CASE_R(13) CASE_R(14) CASE_R(15)
            }
        }
        {
            float4 xv = xv1;
            switch (p1 >> 16) {
                CASE_R(0) CASE_R(1) CASE_R(2) CASE_R(3) CASE_R(4) CASE_R(5) CASE_R(6) CASE_R(7)
                CASE_R(8) CASE_R(9) CASE_R(10) CASE_R(11) CASE_R(12) CASE_R(13) CASE_R(14) CASE_R(15)
            }
        }
    }
    if (e < end) {
        uint32_t p0 = g_sed[e];
        float4 xv = *(const float4*)(x + (size_t)(p0 & 0xFFFF) * 128 + lane * 4);
        switch (p0 >> 16) {
            CASE_R(0) CASE_R(1) CASE_R(2) CASE_R(3) CASE_R(4) CASE_R(5) CASE_R(6) CASE_R(7)
            CASE_R(8) CASE_R(9) CASE_R(10) CASE_R(11) CASE_R(12) CASE_R(13) CASE_R(14) CASE_R(15)
        }
    }

    float inv = 1.0f / fmaxf((float)(end - beg), 1.0f);
#pragma unroll
    for (int r = 0; r < 16; r++) {
        __half2 h0 = __floats2half2_rn(acc[r][0] * inv, acc[r][1] * inv);
        __half2 h1 = __floats2half2_rn(acc[r][2] * inv, acc[r][3] * inv);
        *(uint2*)(out + r * 128 + lane * 4) = make_uint2(h2_as_u32(h0), h2_as_u32(h1));
    }
    float4 xv = *(const float4*)(x + (size_t)n * 128 + lane * 4);
    __half2 h0 = __floats2half2_rn(xv.x, xv.y);
    __half2 h1 = __floats2half2_rn(xv.z, xv.w);
    *(uint2*)(out + 2048 + lane * 4) = make_uint2(h2_as_u32(h0), h2_as_u32(h1));
}

// ---------------- K=2176 streaming GEMM + fused bias/relu/LayerNorm epilogue ----------------
// CTA per 128-row m-tile; loop 17 K-chunks, double-buffered cp.async (A, Bh, Bl).
#define S_A0  0
#define S_A1  32768
#define S_BH0 65536
#define S_BH1 98304
#define S_BL0 131072
#define S_BL1 163840
#define GSMEM2 196608

__device__ __forceinline__ void cpa16(uint32_t dst, const void* src) {
    asm volatile("cp.async.cg.shared.global [%0], [%1], 16;" :: "r"(dst), "l"(src));
}

__device__ __forceinline__ void prefetch_chunk(uint32_t sbase, int buf, int kc, int m0, int t) {
    uint32_t ab = sbase + (buf ? S_A1 : S_A0);
    uint32_t hb = sbase + (buf ? S_BH1 : S_BH0);
    uint32_t lb = sbase + (buf ? S_BL1 : S_BL0);
#pragma unroll
    for (int it = 0; it < 8; it++) {
        int cl = it * 256 + t;
        int row = cl >> 4, c = cl & 15;
        uint32_t soff = row * 256 + ((c ^ (row & 7)) * 16);
        cpa16(ab + soff, g_aggx + (size_t)(m0 + row) * KTOT + kc * 128 + c * 8);
        cpa16(hb + soff, g_Bh2 + (size_t)row * KTOT + kc * 128 + c * 8);
        cpa16(lb + soff, g_Bl2 + (size_t)row * KTOT + kc * 128 + c * 8);
    }
    asm volatile("cp.async.commit_group;");
}

__global__ __launch_bounds__(256, 1) void k_gemm2(const float* __restrict__ bself,
                                                  const float* __restrict__ lg,
                                                  const float* __restrict__ lb,
                                                  float* __restrict__ enc_out,
                                                  int layer, int Nn) {
    extern __shared__ char smem[];
    int t = threadIdx.x, lane = t & 31, w = t >> 5;
    int m0 = blockIdx.x * 128;
    uint32_t sbase = smem_u32(smem);

    prefetch_chunk(sbase, 0, 0, m0, t);

    int wm = (w & 1) * 64, wn = (w >> 1) * 32;
    int atile = lane >> 3, ar = lane & 7;
    int arow_base = wm + ((atile & 1) << 3) + ar;
    int achunk_sel = atile >> 1;
    int bl_ = lane & 15;
    int bhalf = bl_ >> 3, br = bl_ & 7;

    float acc[4][4][4];
#pragma unroll
    for (int i = 0; i < 4; i++)
#pragma unroll
        for (int j = 0; j < 4; j++)
#pragma unroll
            for (int q = 0; q < 4; q++) acc[i][j][q] = 0.0f;

    for (int kc = 0; kc < 17; kc++) {
        int buf = kc & 1;
        uint32_t abase = sbase + (buf ? S_A1 : S_A0);
        uint32_t hbase = sbase + (buf ? S_BH1 : S_BH0);
        uint32_t lbase = sbase + (buf ? S_BL1 : S_BL0);
        asm volatile("cp.async.wait_group 0;");
        __syncthreads();
        if (kc + 1 < 17) prefetch_chunk(sbase, buf ^ 1, kc + 1, m0, t);

#pragma unroll
        for (int ks = 0; ks < 8; ks++) {
            uint32_t a[4][4];
            int ac = ks * 2 + achunk_sel;
#pragma unroll
            for (int i = 0; i < 4; i++) {
                int row = arow_base + i * 16;
                ldm_x4(a[i][0], a[i][1], a[i][2], a[i][3],
                       abase + row * 256 + ((ac ^ (row & 7)) * 16));
            }
            int bc = ks * 2 + bhalf;
            uint32_t bh[4][2], blo[4][2];
#pragma unroll
            for (int j = 0; j < 4; j++) {
                int row = wn + j * 8 + br;
                uint32_t soff = row * 256 + ((bc ^ (row & 7)) * 16);
                ldm_x2(bh[j][0], bh[j][1], hbase + soff);
                ldm_x2(blo[j][0], blo[j][1], lbase + soff);
            }
#pragma unroll
            for (int i = 0; i < 4; i++)
#pragma unroll
                for (int j = 0; j < 4; j++) {
                    mma16816(acc[i][j], a[i][0], a[i][1], a[i][2], a[i][3], bh[j][0], bh[j][1]);
                    mma16816(acc[i][j], a[i][0], a[i][1], a[i][2], a[i][3], blo[j][0], blo[j][1]);
                }
        }
        __syncthreads();
    }

    // stage C in smem (reuses pipeline buffers; all cp.async drained)
    float* cs = (float*)smem;
#pragma unroll
    for (int i = 0; i < 4; i++) {
#pragma unroll
        for (int j = 0; j < 4; j++) {
            int r = wm + i * 16 + (lane >> 2);
            int c = wn + j * 8 + 2 * (lane & 3);
            *(float2*)(cs + r * 136 + c) = make_float2(acc[i][j][0], acc[i][j][1]);
            *(float2*)(cs + (r + 8) * 136 + c) = make_float2(acc[i][j][2], acc[i][j][3]);
        }
    }
    __syncthreads();

    // fused bias + relu + LayerNorm; warp w handles rows w*16 .. w*16+15
    float4 bv = *(const float4*)(bself + lane * 4);
    float4 gv = *(const float4*)(lg + lane * 4);
    float4 b2 = *(const float4*)(lb + lane * 4);
    float* outbase = (layer == 0) ? g_x : enc_out;
#pragma unroll
    for (int i = 0; i < 16; i++) {
        int row = w * 16 + i;
        int gr = m0 + row;
        float4 cv = *(const float4*)(cs + row * 136 + lane * 4);
        float v0 = fmaxf(cv.x + bv.x, 0.f);
        float v1 = fmaxf(cv.y + bv.y, 0.f);
        float v2 = fmaxf(cv.z + bv.z, 0.f);
        float v3 = fmaxf(cv.w + bv.w, 0.f);
        float s = v0 + v1 + v2 + v3;
#pragma unroll
        for (int o = 16; o > 0; o >>= 1) s += __shfl_xor_sync(0xFFFFFFFFu, s, o);
        float mu = s * (1.0f / 128.0f);
        float d0 = v0 - mu, d1 = v1 - mu, d2 = v2 - mu, d3 = v3 - mu;
        float q = d0 * d0 + d1 * d1 + d2 * d2 + d3 * d3;
#pragma unroll
        for (int o = 16; o > 0; o >>= 1) q += __shfl_xor_sync(0xFFFFFFFFu, q, o);
        float rstd = rsqrtf(q * (1.0f / 128.0f) + 1e-5f);
        if (gr < Nn) {
            float4 ov = make_float4(d0 * rstd * gv.x + b2.x, d1 * rstd * gv.y + b2.y,
                                    d2 * rstd * gv.z + b2.z, d3 * rstd * gv.w + b2.w);
            *(float4*)(outbase + (size_t)gr * 128 + lane * 4) = ov;
        }
    }
}

// ---------------- build LSTM input sequence ----------------
__global__ void k_seq(const float* __restrict__ enc, const int* __restrict__ pn,
                      const int* __restrict__ pr, const float* __restrict__ rel) {
    int pl = blockIdx.x;
    int p = pl >> 2, t = pl & 3;
    int d = threadIdx.x;
    int node = pn[p * 4 + t];
    float* o = g_seq + ((size_t)p * 4 + t) * 256;
    o[d] = enc[(size_t)node * 128 + d];
    float rv = 0.0f;
    if (t > 0) { int r = pr[p * 3 + (t - 1)]; rv = rel[r * 128 + d]; }
    o[128 + d] = rv;
}

__global__ void k_wt(const float* __restrict__ Wih_f, const float* __restrict__ Whh_f,
                     const float* __restrict__ Wih_b, const float* __restrict__ Whh_b) {
    int idx = blockIdx.x * blockDim.x + threadIdx.x;
    if (idx >= 2 * 384 * 512) return;
    int dir = idx / (384 * 512);
    int rem = idx % (384 * 512);
    int d = rem / 512, j = rem % 512;
    const float* Wih = dir ? Wih_b : Wih_f;
    const float* Whh = dir ? Whh_b : Whh_f;
    float v = (d < 256) ? Wih[j * 256 + d] : Whh[j * 128 + (d - 256)];
    g_WT[dir][rem] = v;
}

// ---------------- bidirectional LSTM (8 paths per block) ----------------
__global__ __launch_bounds__(512) void k_lstm(const float* __restrict__ bf,
                                              const float* __restrict__ bb) {
    const int PB = 8;
    __shared__ float xt[PB][256];
    __shared__ float hs[PB][128];
    __shared__ float cs[PB][128];
    __shared__ float gs[PB][512];
    int dir = blockIdx.y;
    const float* WT = g_WT[dir];
    const float* bias = dir ? bb : bf;
    int p0 = blockIdx.x * PB;
    int t = threadIdx.x;

    for (int i = t; i < PB * 128; i += 512) { ((float*)hs)[i] = 0.0f; ((float*)cs)[i] = 0.0f; }
    float bj = bias[t];
    __syncthreads();

    for (int step = 0; step < 4; step++) {
        int tt = dir ? (3 - step) : step;
        for (int i = t; i < PB * 256; i += 512) {
            int pp = i >> 8, d = i & 255;
            xt[pp][d] = g_seq[((size_t)(p0 + pp) * 4 + tt) * 256 + d];
        }
        __syncthreads();
        float acc[PB];
#pragma unroll
        for (int p = 0; p < PB; p++) acc[p] = bj;
        for (int d = 0; d < 256; d++) {
            float w = WT[d * 512 + t];
#pragma unroll
            for (int p = 0; p < PB; p++) acc[p] = fmaf(w, xt[p][d], acc[p]);
        }
        for (int d = 0; d < 128; d++) {
            float w = WT[(256 + d) * 512 + t];
#pragma unroll
            for (int p = 0; p < PB; p++) acc[p] = fmaf(w, hs[p][d], acc[p]);
        }
#pragma unroll
        for (int p = 0; p < PB; p++) gs[p][t] = acc[p];
        __syncthreads();
        for (int i = t; i < PB * 128; i += 512) {
            int pp = i >> 7, k = i & 127;
            float ig = 1.0f / (1.0f + expf(-gs[pp][k]));
            float fg = 1.0f / (1.0f + expf(-gs[pp][128 + k]));
            float gg = tanhf(gs[pp][256 + k]);
            float og = 1.0f / (1.0f + expf(-gs[pp][384 + k]));
            float c = fg * cs[pp][k] + ig * gg;
            cs[pp][k] = c;
            hs[pp][k] = og * tanhf(c);
        }
        __syncthreads();
    }
    for (int i = t; i < PB * 128; i += 512) {
        int pp = i >> 7, k = i & 127;
        g_h[((size_t)dir * 256 + p0 + pp) * 128 + k] = hs[pp][k];
    }
}

// ---------------- output head ----------------
__global__ void k_head(const float* __restrict__ Wop, const float* __restrict__ bop,
                       const float* __restrict__ q, const float* __restrict__ Ws1,
                       const float* __restrict__ bs1, const float* __restrict__ Ws2,
                       const float* __restrict__ bs2,
                       float* __restrict__ pe_out, float* __restrict__ sim_out) {
    int p = blockIdx.x;
    int k = threadIdx.x;
    __shared__ float cat[256];
    __shared__ float cat2[256];
    __shared__ float red[4];
    cat[k]       = g_h[(size_t)p * 128 + k];
    cat[128 + k] = g_h[(size_t)(256 + p) * 128 + k];
    __syncthreads();
    float acc = bop[k];
    for (int j = 0; j < 256; j++) acc = fmaf(cat[j], Wop[k * 256 + j], acc);
    float pe = fmaxf(acc, 0.0f);
    pe_out[(size_t)p * 128 + k] = pe;
    cat2[k] = pe;
    cat2[128 + k] = q[k];
    __syncthreads();
    float a2 = bs1[k];
    for (int j = 0; j < 256; j++) a2 = fmaf(cat2[j], Ws1[k * 256 + j], a2);
    float hdn = fmaxf(a2, 0.0f);
    float s = hdn * Ws2[k];
#pragma unroll
    for (int o = 16; o > 0; o >>= 1) s += __shfl_xor_sync(0xFFFFFFFFu, s, o);
    if ((k & 31) == 0) red[k >> 5] = s;
    __syncthreads();
    if (k == 0) {
        float tot = red[0] + red[1] + red[2] + red[3] + bs2[0];
        sim_out[p] = 1.0f / (1.0f + expf(-tot));
    }
}

// ---------------- launch ----------------
extern "C" void kernel_launch(void* const* d_in, const int* in_sizes, int n_in,
                              void* d_out, int out_size) {
    const float* node_features = (const float*)d_in[0];
    const int*   edge_index    = (const int*)d_in[1];
    const int*   edge_types    = (const int*)d_in[2];
    const float* query         = (const float*)d_in[3];
    const int*   path_nodes    = (const int*)d_in[4];
    const int*   path_rel      = (const int*)d_in[5];
    const float* W_self        = (const float*)d_in[6];
    const float* b_self        = (const float*)d_in[7];
    const float* W_rel         = (const float*)d_in[8];
    const float* ln_g          = (const float*)d_in[9];
    const float* ln_b          = (const float*)d_in[10];
    const float* rel_emb       = (const float*)d_in[11];
    const float* W_ih_f        = (const float*)d_in[12];
    const float* W_hh_f        = (const float*)d_in[13];
    const float* b_f           = (const float*)d_in[14];
    const float* W_ih_b        = (const float*)d_in[15];
    const float* W_hh_b        = (const float*)d_in[16];
    const float* b_b           = (const float*)d_in[17];
    const float* W_op          = (const float*)d_in[18];
    const float* b_op          = (const float*)d_in[19];
    const float* W_s1          = (const float*)d_in[20];
    const float* b_s1          = (const float*)d_in[21];
    const float* W_s2          = (const float*)d_in[22];
    const float* b_s2          = (const float*)d_in[23];
    (void)n_in; (void)out_size;

    const int N = in_sizes[0] / 128;
    const int E = in_sizes[1] / 2;
    const int P = in_sizes[4] / 4;

    float* out     = (float*)d_out;
    float* enc_out = out;
    float* pe_out  = out + (size_t)N * 128;
    float* sim_out = pe_out + (size_t)P * 128;

    const int* src = edge_index;
    const int* dst = edge_index + E;

    cudaFuncSetAttribute(k_gemm2, cudaFuncAttributeMaxDynamicSharedMemorySize, GSMEM2);

    // CSR build (once per call)
    k_zero_cnt<<<(N + 255) / 256, 256>>>(N);
    k_hist<<<(E + 255) / 256, 256>>>(dst, E);
    k_scan<<<1, 1024>>>(N);
    k_place<<<(E + 255) / 256, 256>>>(src, dst, edge_types, E);

    for (int l = 0; l < 2; l++) {
        k_packb2<<<(128 * KTOT + 255) / 256, 256>>>(W_rel + (size_t)l * R * 128 * 128,
                                                    W_self + (size_t)l * 128 * 128);
        k_aggr<<<(MPAD + 7) / 8, 256>>>(node_features, l, N);
        k_gemm2<<<MPAD / 128, 256, GSMEM2>>>(b_self + l * 128, ln_g + l * 128, ln_b + l * 128,
                                             enc_out, l, N);
    }

    k_seq<<<P * 4, 128>>>(enc_out, path_nodes, path_rel, rel_emb);
    k_wt<<<(2 * 384 * 512 + 255) / 256, 256>>>(W_ih_f, W_hh_f, W_ih_b, W_hh_b);
    k_lstm<<<dim3(P / 8, 2), 512>>>(b_f, b_b);
    k_head<<<P, 128>>>(W_op, b_op, query, W_s1, b_s1, W_s2, b_s2, pe_out, sim_out);
}

// round 9
// speedup vs baseline: 1.1435x; 1.1435x over previous
#include <cuda_runtime.h>
#include <cuda_fp16.h>
#include <math.h>
#include <stdint.h>

#define D 128
#define R 16
#define NCOL 2176
#define MPAD 50048         // 391 * 128
#define NMAX 50000
#define EMAX 800000

// ---------------- scratch (device globals; allocation-free) ----------------
__device__ __half g_trans16[(size_t)MPAD * 2048];  // 204 MB, relation messages
__device__ float g_self[(size_t)MPAD * 128];
__device__ __half g_Ah[(size_t)MPAD * 128];
__device__ __half g_Al[(size_t)MPAD * 128];
__device__ __half g_Bh[NCOL * 128];                 // [n][k]
__device__ float g_seq[256 * 4 * 256];
__device__ float g_WT[2][384 * 512];
__device__ float g_h[2 * 256 * 128];
// CSR
__device__ int g_cnt[NMAX];
__device__ int g_off[NMAX + 1];
__device__ int g_cur[NMAX];
__device__ uint32_t g_sed[EMAX];   // packed src | (r<<16)

// ---------------- bit-cast helpers ----------------
__device__ __forceinline__ uint32_t h2_as_u32(__half2 h) {
    uint32_t u; *(__half2*)&u = h; return u;
}
__device__ __forceinline__ __half2 u32_as_h2(uint32_t u) {
    __half2 h; *(uint32_t*)&h = u; return h;
}

// ---------------- PTX helpers ----------------
__device__ __forceinline__ uint32_t smem_u32(const void* p) {
    return (uint32_t)__cvta_generic_to_shared(p);
}
__device__ __forceinline__ void ldm_x4(uint32_t& r0, uint32_t& r1, uint32_t& r2, uint32_t& r3,
                                       uint32_t a) {
    asm volatile("ldmatrix.sync.aligned.m8n8.x4.shared.b16 {%0,%1,%2,%3}, [%4];"
                 : "=r"(r0), "=r"(r1), "=r"(r2), "=r"(r3) : "r"(a));
}
__device__ __forceinline__ void ldm_x2(uint32_t& r0, uint32_t& r1, uint32_t a) {
    asm volatile("ldmatrix.sync.aligned.m8n8.x2.shared.b16 {%0,%1}, [%2];"
                 : "=r"(r0), "=r"(r1) : "r"(a));
}
__device__ __forceinline__ void mma16816(float* c, uint32_t a0, uint32_t a1, uint32_t a2,
                                         uint32_t a3, uint32_t b0, uint32_t b1) {
    asm volatile(
        "mma.sync.aligned.m16n8k16.row.col.f32.f16.f16.f32 "
        "{%0,%1,%2,%3}, {%4,%5,%6,%7}, {%8,%9}, {%0,%1,%2,%3};"
        : "+f"(c[0]), "+f"(c[1]), "+f"(c[2]), "+f"(c[3])
        : "r"(a0), "r"(a1), "r"(a2), "r"(a3), "r"(b0), "r"(b1));
}

// ---------------- CSR build ----------------
__global__ void k_zero_cnt(int N) {
    int i = blockIdx.x * blockDim.x + threadIdx.x;
    if (i < N) g_cnt[i] = 0;
}
__global__ void k_hist(const int* __restrict__ dst, int E) {
    int e = blockIdx.x * blockDim.x + threadIdx.x;
    if (e < E) atomicAdd(&g_cnt[dst[e]], 1);
}
__global__ __launch_bounds__(1024) void k_scan(int N) {
    __shared__ int sh[1024];
    int t = threadIdx.x;
    int chunk = (N + 1023) / 1024;
    int c0 = t * chunk, c1 = min(c0 + chunk, N);
    int s = 0;
    for (int i = c0; i < c1; i++) s += g_cnt[i];
    sh[t] = s;
    __syncthreads();
    for (int o = 1; o < 1024; o <<= 1) {
        int v = (t >= o) ? sh[t - o] : 0;
        __syncthreads();
        sh[t] += v;
        __syncthreads();
    }
    int run = sh[t] - s;
    for (int i = c0; i < c1; i++) {
        g_off[i] = run;
        g_cur[i] = run;
        run += g_cnt[i];
    }
    if (t == 1023) g_off[N] = run;
}
__global__ void k_place(const int* __restrict__ src, const int* __restrict__ dst,
                        const int* __restrict__ et, int E) {
    int e = blockIdx.x * blockDim.x + threadIdx.x;
    if (e >= E) return;
    int pos = atomicAdd(&g_cur[dst[e]], 1);
    g_sed[pos] = (uint32_t)src[e] | ((uint32_t)et[e] << 16);
}

// ---------------- conversions ----------------
// node_features (fp32) -> fp16 hi/lo split, padded rows zeroed (runs once, before layer 0)
__global__ void k_conv(const float* __restrict__ x0, int Nn) {
    int i4 = blockIdx.x * blockDim.x + threadIdx.x;
    if (i4 >= MPAD * 32) return;
    int row = i4 >> 5;
    float4 v = make_float4(0.f, 0.f, 0.f, 0.f);
    if (row < Nn) v = *(const float4*)(x0 + (size_t)i4 * 4);
    __half2 h0 = __floats2half2_rn(v.x, v.y);
    __half2 h1 = __floats2half2_rn(v.z, v.w);
    float2 f0 = __half22float2(h0), f1 = __half22float2(h1);
    __half2 l0 = __floats2half2_rn(v.x - f0.x, v.y - f0.y);
    __half2 l1 = __floats2half2_rn(v.z - f1.x, v.w - f1.y);
    ((uint2*)g_Ah)[i4] = make_uint2(h2_as_u32(h0), h2_as_u32(h1));
    ((uint2*)g_Al)[i4] = make_uint2(h2_as_u32(l0), h2_as_u32(l1));
}

__global__ void k_packb(const float* __restrict__ Wrel, const float* __restrict__ Wself) {
    int idx = blockIdx.x * blockDim.x + threadIdx.x;
    if (idx >= NCOL * 128) return;
    int n = idx >> 7, d = idx & 127;
    float v;
    if (n < 2048) {
        int r = n >> 7, k = n & 127;
        v = Wrel[((size_t)r * 128 + d) * 128 + k];
    } else {
        v = Wself[d * 128 + (n - 2048)];
    }
    g_Bh[idx] = __float2half_rn(v);
}

// ---------------- A-resident pipelined GEMM (R7 structure) ----------------
#define SM_AH 0
#define SM_AL 32768
#define SM_B0 65536
#define SM_B1 98304
#define SM_C  131072
#define GSMEM (131072 + 69632)

__device__ __forceinline__ void load_tile(char* dstbase, const __half* g, int row0, int t) {
#pragma unroll
    for (int it = 0; it < 8; it++) {
        int cl = it * 256 + t;
        int row = cl >> 4, c = cl & 15;
        uint4 v = *(const uint4*)(g + (size_t)(row0 + row) * 128 + c * 8);
        *(uint4*)(dstbase + row * 256 + ((c ^ (row & 7)) * 16)) = v;
    }
}

__device__ __forceinline__ void prefetch_b(uint32_t dstb, const __half* gsrc, int t) {
#pragma unroll
    for (int it = 0; it < 8; it++) {
        int cl = it * 256 + t;
        int row = cl >> 4, c = cl & 15;
        const void* src = gsrc + (size_t)row * 128 + c * 8;
        uint32_t dst = dstb + row * 256 + ((c ^ (row & 7)) * 16);
        asm volatile("cp.async.cg.shared.global [%0], [%1], 16;" :: "r"(dst), "l"(src));
    }
    asm volatile("cp.async.commit_group;");
}

__global__ __launch_bounds__(256, 1) void k_gemm() {
    extern __shared__ char smem[];
    int t = threadIdx.x, lane = t & 31, w = t >> 5;
    int m0 = blockIdx.x * 128;
    uint32_t sbase = smem_u32(smem);

    prefetch_b(sbase + SM_B0, g_Bh, t);
    load_tile(smem + SM_AH, g_Ah, m0, t);
    load_tile(smem + SM_AL, g_Al, m0, t);

    int wm = (w & 1) * 64, wn = (w >> 1) * 32;
    int atile = lane >> 3, ar = lane & 7;
    int arow_base = wm + ((atile & 1) << 3) + ar;
    int achunk_sel = atile >> 1;
    int bl = lane & 15;
    int bhalf = bl >> 3, br = bl & 7;

    for (int n = 0; n < 17; n++) {
        uint32_t bbase = sbase + ((n & 1) ? SM_B1 : SM_B0);
        asm volatile("cp.async.wait_group 0;");
        __syncthreads();
        if (n + 1 < 17) {
            prefetch_b(sbase + (((n + 1) & 1) ? SM_B1 : SM_B0),
                       g_Bh + (size_t)(n + 1) * 128 * 128, t);
        }

        float acc[4][4][4];
#pragma unroll
        for (int i = 0; i < 4; i++)
#pragma unroll
            for (int j = 0; j < 4; j++)
#pragma unroll
                for (int q = 0; q < 4; q++) acc[i][j][q] = 0.0f;

#pragma unroll
        for (int pass = 0; pass < 2; pass++) {
            uint32_t abase = sbase + (pass ? SM_AL : SM_AH);
#pragma unroll
            for (int ks = 0; ks < 8; ks++) {
                uint32_t a[4][4];
                uint32_t b[4][2];
                int ac = ks * 2 + achunk_sel;
#pragma unroll
                for (int i = 0; i < 4; i++) {
                    int row = arow_base + i * 16;
                    uint32_t addr = abase + row * 256 + ((ac ^ (row & 7)) * 16);
                    ldm_x4(a[i][0], a[i][1], a[i][2], a[i][3], addr);
                }
                int bc = ks * 2 + bhalf;
#pragma unroll
                for (int j = 0; j < 4; j++) {
                    int row = wn + j * 8 + br;
                    uint32_t addr = bbase + row * 256 + ((bc ^ (row & 7)) * 16);
                    ldm_x2(b[j][0], b[j][1], addr);
                }
#pragma unroll
                for (int i = 0; i < 4; i++)
#pragma unroll
                    for (int j = 0; j < 4; j++)
                        mma16816(acc[i][j], a[i][0], a[i][1], a[i][2], a[i][3], b[j][0], b[j][1]);
            }
        }
        __syncthreads();

        float* cs = (float*)(smem + SM_C);
#pragma unroll
        for (int i = 0; i < 4; i++) {
#pragma unroll
            for (int j = 0; j < 4; j++) {
                int r = wm + i * 16 + (lane >> 2);
                int c = wn + j * 8 + 2 * (lane & 3);
                *(float2*)(cs + r * 136 + c) = make_float2(acc[i][j][0], acc[i][j][1]);
                *(float2*)(cs + (r + 8) * 136 + c) = make_float2(acc[i][j][2], acc[i][j][3]);
            }
        }
        __syncthreads();

        if (n < 16) {
#pragma unroll
            for (int it = 0; it < 16; it++) {
                int idx = it * 256 + t;
                int row = idx >> 5, c4 = (idx & 31) * 4;
                float4 v = *(const float4*)(cs + row * 136 + c4);
                __half2 h0 = __floats2half2_rn(v.x, v.y);
                __half2 h1 = __floats2half2_rn(v.z, v.w);
                *(uint2*)(g_trans16 + (size_t)(m0 + row) * 2048 + n * 128 + c4) =
                    make_uint2(h2_as_u32(h0), h2_as_u32(h1));
            }
        } else {
#pragma unroll
            for (int it = 0; it < 16; it++) {
                int idx = it * 256 + t;
                int row = idx >> 5, c4 = (idx & 31) * 4;
                float4 v = *(const float4*)(cs + row * 136 + c4);
                *(float4*)(g_self + (size_t)(m0 + row) * 128 + c4) = v;
            }
        }
    }
}

// ---------------- fused gather + update: warp per node, half-warp per edge ----------------
__device__ __forceinline__ void acc8(float* a, uint4 r) {
    float2 f;
    f = __half22float2(u32_as_h2(r.x)); a[0] += f.x; a[1] += f.y;
    f = __half22float2(u32_as_h2(r.y)); a[2] += f.x; a[3] += f.y;
    f = __half22float2(u32_as_h2(r.z)); a[4] += f.x; a[5] += f.y;
    f = __half22float2(u32_as_h2(r.w)); a[6] += f.x; a[7] += f.y;
}

__global__ __launch_bounds__(256) void k_gather(const float* __restrict__ bself,
                                                const float* __restrict__ lg,
                                                const float* __restrict__ lb,
                                                float* __restrict__ enc_out,
                                                int layer, int M) {
    int n = blockIdx.x * 8 + (threadIdx.x >> 5);
    int lane = threadIdx.x & 31;
    if (n >= M) return;
    int half = lane >> 4, hl = lane & 15;
    int beg = g_off[n], end = g_off[n + 1];

    float acc[8];
#pragma unroll
    for (int q = 0; q < 8; q++) acc[q] = 0.0f;

    // half-warp h handles edges beg+h, beg+h+2, ... ; 16 lanes x 16B = one 256B message
    int e = beg + half;
    for (; e + 6 < end; e += 8) {
        uint32_t p0 = g_sed[e], p1 = g_sed[e + 2], p2 = g_sed[e + 4], p3 = g_sed[e + 6];
        uint4 r0 = *(const uint4*)(g_trans16 + (size_t)(p0 & 0xFFFF) * 2048 + ((p0 >> 16) << 7) + hl * 8);
        uint4 r1 = *(const uint4*)(g_trans16 + (size_t)(p1 & 0xFFFF) * 2048 + ((p1 >> 16) << 7) + hl * 8);
        uint4 r2 = *(const uint4*)(g_trans16 + (size_t)(p2 & 0xFFFF) * 2048 + ((p2 >> 16) << 7) + hl * 8);
        uint4 r3 = *(const uint4*)(g_trans16 + (size_t)(p3 & 0xFFFF) * 2048 + ((p3 >> 16) << 7) + hl * 8);
        acc8(acc, r0); acc8(acc, r1); acc8(acc, r2); acc8(acc, r3);
    }
    for (; e < end; e += 2) {
        uint32_t p = g_sed[e];
        uint4 r = *(const uint4*)(g_trans16 + (size_t)(p & 0xFFFF) * 2048 + ((p >> 16) << 7) + hl * 8);
        acc8(acc, r);
    }
    // combine the two half-warps (both now hold the full sum for dims hl*8..hl*8+7)
#pragma unroll
    for (int q = 0; q < 8; q++) acc[q] += __shfl_xor_sync(0xFFFFFFFFu, acc[q], 16);

    float inv = 1.0f / fmaxf((float)(end - beg), 1.0f);
    float4 s0 = *(const float4*)(g_self + (size_t)n * 128 + hl * 8);
    float4 s1 = *(const float4*)(g_self + (size_t)n * 128 + hl * 8 + 4);
    float4 b0 = *(const float4*)(bself + hl * 8);
    float4 b1 = *(const float4*)(bself + hl * 8 + 4);
    float v[8];
    v[0] = fmaxf(s0.x + b0.x + acc[0] * inv, 0.f);
    v[1] = fmaxf(s0.y + b0.y + acc[1] * inv, 0.f);
    v[2] = fmaxf(s0.z + b0.z + acc[2] * inv, 0.f);
    v[3] = fmaxf(s0.w + b0.w + acc[3] * inv, 0.f);
    v[4] = fmaxf(s1.x + b1.x + acc[4] * inv, 0.f);
    v[5] = fmaxf(s1.y + b1.y + acc[5] * inv, 0.f);
    v[6] = fmaxf(s1.z + b1.z + acc[6] * inv, 0.f);
    v[7] = fmaxf(s1.w + b1.w + acc[7] * inv, 0.f);

    float s = 0.f;
#pragma unroll
    for (int q = 0; q < 8; q++) s += v[q];
#pragma unroll
    for (int o = 1; o < 16; o <<= 1) s += __shfl_xor_sync(0xFFFFFFFFu, s, o);
    float mu = s * (1.0f / 128.0f);
    float qs = 0.f;
    float dv[8];
#pragma unroll
    for (int q = 0; q < 8; q++) { dv[q] = v[q] - mu; qs += dv[q] * dv[q]; }
#pragma unroll
    for (int o = 1; o < 16; o <<= 1) qs += __shfl_xor_sync(0xFFFFFFFFu, qs, o);
    float rstd = rsqrtf(qs * (1.0f / 128.0f) + 1e-5f);

    float4 g0 = *(const float4*)(lg + hl * 8);
    float4 g1 = *(const float4*)(lg + hl * 8 + 4);
    float4 p0 = *(const float4*)(lb + hl * 8);
    float4 p1 = *(const float4*)(lb + hl * 8 + 4);
    float ov[8];
    ov[0] = dv[0] * rstd * g0.x + p0.x; ov[1] = dv[1] * rstd * g0.y + p0.y;
    ov[2] = dv[2] * rstd * g0.z + p0.z; ov[3] = dv[3] * rstd * g0.w + p0.w;
    ov[4] = dv[4] * rstd * g1.x + p1.x; ov[5] = dv[5] * rstd * g1.y + p1.y;
    ov[6] = dv[6] * rstd * g1.z + p1.z; ov[7] = dv[7] * rstd * g1.w + p1.w;

    if (half == 0) {
        if (layer == 0) {
            // write fp16 hi/lo directly (feeds layer-1 GEMM); padding rows stay zero
            __half2 h0 = __floats2half2_rn(ov[0], ov[1]);
            __half2 h1 = __floats2half2_rn(ov[2], ov[3]);
            __half2 h2 = __floats2half2_rn(ov[4], ov[5]);
            __half2 h3 = __floats2half2_rn(ov[6], ov[7]);
            float2 f0 = __half22float2(h0), f1 = __half22float2(h1);
            float2 f2 = __half22float2(h2), f3 = __half22float2(h3);
            __half2 l0 = __floats2half2_rn(ov[0] - f0.x, ov[1] - f0.y);
            __half2 l1 = __floats2half2_rn(ov[2] - f1.x, ov[3] - f1.y);
            __half2 l2 = __floats2half2_rn(ov[4] - f2.x, ov[5] - f2.y);
            __half2 l3 = __floats2half2_rn(ov[6] - f3.x, ov[7] - f3.y);
            *(uint4*)(g_Ah + (size_t)n * 128 + hl * 8) =
                make_uint4(h2_as_u32(h0), h2_as_u32(h1), h2_as_u32(h2), h2_as_u32(h3));
            *(uint4*)(g_Al + (size_t)n * 128 + hl * 8) =
                make_uint4(h2_as_u32(l0), h2_as_u32(l1), h2_as_u32(l2), h2_as_u32(l3));
        } else {
            *(float4*)(enc_out + (size_t)n * 128 + hl * 8) =
                make_float4(ov[0], ov[1], ov[2], ov[3]);
            *(float4*)(enc_out + (size_t)n * 128 + hl * 8 + 4) =
                make_float4(ov[4], ov[5], ov[6], ov[7]);
        }
    }
}

// ---------------- build LSTM input sequence ----------------
__global__ void k_seq(const float* __restrict__ enc, const int* __restrict__ pn,
                      const int* __restrict__ pr, const float* __restrict__ rel) {
    int pl = blockIdx.x;
    int p = pl >> 2, t = pl & 3;
    int d = threadIdx.x;
    int node = pn[p * 4 + t];
    float* o = g_seq + ((size_t)p * 4 + t) * 256;
    o[d] = enc[(size_t)node * 128 + d];
    float rv = 0.0f;
    if (t > 0) { int r = pr[p * 3 + (t - 1)]; rv = rel[r * 128 + d]; }
    o[128 + d] = rv;
}

__global__ void k_wt(const float* __restrict__ Wih_f, const float* __restrict__ Whh_f,
                     const float* __restrict__ Wih_b, const float* __restrict__ Whh_b) {
    int idx = blockIdx.x * blockDim.x + threadIdx.x;
    if (idx >= 2 * 384 * 512) return;
    int dir = idx / (384 * 512);
    int rem = idx % (384 * 512);
    int d = rem / 512, j = rem % 512;
    const float* Wih = dir ? Wih_b : Wih_f;
    const float* Whh = dir ? Whh_b : Whh_f;
    float v = (d < 256) ? Wih[j * 256 + d] : Whh[j * 128 + (d - 256)];
    g_WT[dir][rem] = v;
}

// ---------------- bidirectional LSTM (8 paths per block) ----------------
__global__ __launch_bounds__(512) void k_lstm(const float* __restrict__ bf,
                                              const float* __restrict__ bb) {
    const int PB = 8;
    __shared__ float xt[PB][256];
    __shared__ float hs[PB][128];
    __shared__ float cs[PB][128];
    __shared__ float gs[PB][512];
    int dir = blockIdx.y;
    const float* WT = g_WT[dir];
    const float* bias = dir ? bb : bf;
    int p0 = blockIdx.x * PB;
    int t = threadIdx.x;

    for (int i = t; i < PB * 128; i += 512) { ((float*)hs)[i] = 0.0f; ((float*)cs)[i] = 0.0f; }
    float bj = bias[t];
    __syncthreads();

    for (int step = 0; step < 4; step++) {
        int tt = dir ? (3 - step) : step;
        for (int i = t; i < PB * 256; i += 512) {
            int pp = i >> 8, d = i & 255;
            xt[pp][d] = g_seq[((size_t)(p0 + pp) * 4 + tt) * 256 + d];
        }
        __syncthreads();
        float acc[PB];
#pragma unroll
        for (int p = 0; p < PB; p++) acc[p] = bj;
        for (int d = 0; d < 256; d++) {
            float w = WT[d * 512 + t];
#pragma unroll
            for (int p = 0; p < PB; p++) acc[p] = fmaf(w, xt[p][d], acc[p]);
        }
        for (int d = 0; d < 128; d++) {
            float w = WT[(256 + d) * 512 + t];
#pragma unroll
            for (int p = 0; p < PB; p++) acc[p] = fmaf(w, hs[p][d], acc[p]);
        }
#pragma unroll
        for (int p = 0; p < PB; p++) gs[p][t] = acc[p];
        __syncthreads();
        for (int i = t; i < PB * 128; i += 512) {
            int pp = i >> 7, k = i & 127;
            float ig = 1.0f / (1.0f + expf(-gs[pp][k]));
            float fg = 1.0f / (1.0f + expf(-gs[pp][128 + k]));
            float gg = tanhf(gs[pp][256 + k]);
            float og = 1.0f / (1.0f + expf(-gs[pp][384 + k]));
            float c = fg * cs[pp][k] + ig * gg;
            cs[pp][k] = c;
            hs[pp][k] = og * tanhf(c);
        }
        __syncthreads();
    }
    for (int i = t; i < PB * 128; i += 512) {
        int pp = i >> 7, k = i & 127;
        g_h[((size_t)dir * 256 + p0 + pp) * 128 + k] = hs[pp][k];
    }
}

// ---------------- output head ----------------
__global__ void k_head(const float* __restrict__ Wop, const float* __restrict__ bop,
                       const float* __restrict__ q, const float* __restrict__ Ws1,
                       const float* __restrict__ bs1, const float* __restrict__ Ws2,
                       const float* __restrict__ bs2,
                       float* __restrict__ pe_out, float* __restrict__ sim_out) {
    int p = blockIdx.x;
    int k = threadIdx.x;
    __shared__ float cat[256];
    __shared__ float cat2[256];
    __shared__ float red[4];
    cat[k]       = g_h[(size_t)p * 128 + k];
    cat[128 + k] = g_h[(size_t)(256 + p) * 128 + k];
    __syncthreads();
    float acc = bop[k];
    for (int j = 0; j < 256; j++) acc = fmaf(cat[j], Wop[k * 256 + j], acc);
    float pe = fmaxf(acc, 0.0f);
    pe_out[(size_t)p * 128 + k] = pe;
    cat2[k] = pe;
    cat2[128 + k] = q[k];
    __syncthreads();
    float a2 = bs1[k];
    for (int j = 0; j < 256; j++) a2 = fmaf(cat2[j], Ws1[k * 256 + j], a2);
    float hdn = fmaxf(a2, 0.0f);
    float s = hdn * Ws2[k];
#pragma unroll
    for (int o = 16; o > 0; o >>= 1) s += __shfl_xor_sync(0xFFFFFFFFu, s, o);
    if ((k & 31) == 0) red[k >> 5] = s;
    __syncthreads();
    if (k == 0) {
        float tot = red[0] + red[1] + red[2] + red[3] + bs2[0];
        sim_out[p] = 1.0f / (1.0f + expf(-tot));
    }
}

// ---------------- launch ----------------
extern "C" void kernel_launch(void* const* d_in, const int* in_sizes, int n_in,
                              void* d_out, int out_size) {
    const float* node_features = (const float*)d_in[0];
    const int*   edge_index    = (const int*)d_in[1];
    const int*   edge_types    = (const int*)d_in[2];
    const float* query         = (const float*)d_in[3];
    const int*   path_nodes    = (const int*)d_in[4];
    const int*   path_rel      = (const int*)d_in[5];
    const float* W_self        = (const float*)d_in[6];
    const float* b_self        = (const float*)d_in[7];
    const float* W_rel         = (const float*)d_in[8];
    const float* ln_g          = (const float*)d_in[9];
    const float* ln_b          = (const float*)d_in[10];
    const float* rel_emb       = (const float*)d_in[11];
    const float* W_ih_f        = (const float*)d_in[12];
    const float* W_hh_f        = (const float*)d_in[13];
    const float* b_f           = (const float*)d_in[14];
    const float* W_ih_b        = (const float*)d_in[15];
    const float* W_hh_b        = (const float*)d_in[16];
    const float* b_b           = (const float*)d_in[17];
    const float* W_op          = (const float*)d_in[18];
    const float* b_op          = (const float*)d_in[19];
    const float* W_s1          = (const float*)d_in[20];
    const float* b_s1          = (const float*)d_in[21];
    const float* W_s2          = (const float*)d_in[22];
    const float* b_s2          = (const float*)d_in[23];
    (void)n_in; (void)out_size;

    const int N = in_sizes[0] / 128;
    const int E = in_sizes[1] / 2;
    const int P = in_sizes[4] / 4;

    float* out     = (float*)d_out;
    float* enc_out = out;
    float* pe_out  = out + (size_t)N * 128;
    float* sim_out = pe_out + (size_t)P * 128;

    const int* src = edge_index;
    const int* dst = edge_index + E;

    cudaFuncSetAttribute(k_gemm, cudaFuncAttributeMaxDynamicSharedMemorySize, GSMEM);

    // CSR build (once per call)
    k_zero_cnt<<<(N + 255) / 256, 256>>>(N);
    k_hist<<<(E + 255) / 256, 256>>>(dst, E);
    k_scan<<<1, 1024>>>(N);
    k_place<<<(E + 255) / 256, 256>>>(src, dst, edge_types, E);

    // fp16 split of layer-0 input (also zeroes padding rows for both layers)
    k_conv<<<(MPAD * 32 + 255) / 256, 256>>>(node_features, N);

    for (int l = 0; l < 2; l++) {
        k_packb<<<(NCOL * 128 + 255) / 256, 256>>>(W_rel + (size_t)l * R * 128 * 128,
                                                   W_self + (size_t)l * 128 * 128);
        k_gemm<<<MPAD / 128, 256, GSMEM>>>();
        k_gather<<<(N + 7) / 8, 256>>>(b_self + l * 128, ln_g + l * 128, ln_b + l * 128,
                                       enc_out, l, N);
    }

    k_seq<<<P * 4, 128>>>(enc_out, path_nodes, path_rel, rel_emb);
    k_wt<<<(2 * 384 * 512 + 255) / 256, 256>>>(W_ih_f, W_hh_f, W_ih_b, W_hh_b);
    k_lstm<<<dim3(P / 8, 2), 512>>>(b_f, b_b);
    k_head<<<P, 128>>>(W_op, b_op, query, W_s1, b_s1, W_s2, b_s2, pe_out, sim_out);
}